// round 16
// baseline (speedup 1.0000x reference)
#include <cuda_runtime.h>
#include <cuda_fp16.h>
#include <cstdint>
#include <cstddef>

typedef unsigned int u32;
typedef unsigned short u16;

#define BN 4
#define TT 2048
#define CC 1024
#define MROWS (BN*TT)   // 8192

// ======================= device scratch (no allocs allowed) =======================
__device__ __align__(256) __half g_xh[MROWS*CC];
__device__ __align__(256) __half g_wh[4*CC*CC];
__device__ __align__(256) __half g_q [MROWS*CC];
__device__ __align__(256) __half g_k [MROWS*CC];
__device__ __align__(256) __half g_vt[MROWS*CC];                 // V^T [b][d][s]
__device__ __align__(256) float  g_s [(size_t)BN*TT*TT];
__device__ __align__(256) __half g_p [(size_t)BN*TT*TT];
__device__ __align__(256) __half g_c [MROWS*CC];

// ======================= PTX helpers (sm_100 baseline, NO 'a' features) =======================
__device__ __forceinline__ u32 smem_u32(const void* p) {
    u32 a;
    asm("{ .reg .u64 t; cvta.to.shared.u64 t, %1; cvt.u32.u64 %0, t; }" : "=r"(a) : "l"(p));
    return a;
}
__device__ __forceinline__ void cpa16(u32 dst, const void* src) {
    asm volatile("cp.async.cg.shared.global [%0], [%1], 16;" :: "r"(dst), "l"(src) : "memory");
}
#define CP_COMMIT() asm volatile("cp.async.commit_group;" ::: "memory")
#define CP_WAIT(n)  asm volatile("cp.async.wait_group %0;" :: "n"(n) : "memory")

#define LDSM4(d0,d1,d2,d3,a) \
    asm volatile("ldmatrix.sync.aligned.m8n8.x4.shared.b16 {%0,%1,%2,%3}, [%4];" \
                 : "=r"(d0),"=r"(d1),"=r"(d2),"=r"(d3) : "r"(a))

__device__ __forceinline__ void mma_f16(float* c, const u32* a, const u32* b) {
    asm volatile(
        "mma.sync.aligned.m16n8k16.row.col.f32.f16.f16.f32 "
        "{%0,%1,%2,%3}, {%4,%5,%6,%7}, {%8,%9}, {%0,%1,%2,%3};"
        : "+f"(c[0]), "+f"(c[1]), "+f"(c[2]), "+f"(c[3])
        : "r"(a[0]), "r"(a[1]), "r"(a[2]), "r"(a[3]), "r"(b[0]), "r"(b[1]));
}

__device__ __forceinline__ u32 pack_h2(__half a, __half b) {
    __half2 t = __halves2half2(a, b);
    return *reinterpret_cast<u32*>(&t);
}
__device__ __forceinline__ u16 h_bits(__half h) {
    return *reinterpret_cast<u16*>(&h);
}

// ======================= GEMM kernel =======================
// Tile 128x128, K-chunk 64 (half), 128 threads (4 warps, 2x2 grid, 64x64 warp tile).
// Stage row = 64 halves = 128B (full SW128). Stage A(16K)+B(16K)=32KB; 2 stages.
// 65KB smem, <=168 regs -> 3 CTAs/SM.
#define ST_BYTES   32768u
#define NSTAGE     2
#define SMEM_BYTES (1024 + NSTAGE*32768)   // 66560

// MODE 0: half out (+optional bias, +batch stride on C)         [Q,K,P->ctx]
// MODE 1: V-projection: bias then transposed half store into vt[b][d][s]
// MODE 2: fp32 * scale out (+batch stride on C)                 [scores]
// MODE 3: fp32 + bias out (final output)
template<int MODE>
__global__ void __launch_bounds__(128, 3) gemm_f16(
    const __half* __restrict__ A, const __half* __restrict__ B,
    int lda, int ldb, int K,
    long long sAz, long long sBz, long long sCz,
    const float* __restrict__ bias, float scale,
    __half* __restrict__ outH, float* __restrict__ outF, int ldc)
{
    extern __shared__ __align__(1024) char smem_raw[];
    const u32 sb0 = smem_u32(smem_raw);
    const u32 sb  = (sb0 + 1023u) & ~1023u;
    char* smem_ptr = smem_raw + (sb - sb0);

    const int tid  = threadIdx.x;
    const int lane = tid & 31, wid = tid >> 5;
    const int wm = wid & 1, wn = wid >> 1;          // 2 x 2 warp grid, 64x64 tiles
    const int m0 = blockIdx.x * 128, n0 = blockIdx.y * 128;
    const long long z = blockIdx.z;
    A += z * sAz; B += z * sBz;

    float acc[4][8][4];
    #pragma unroll
    for (int i = 0; i < 4; ++i)
        #pragma unroll
        for (int j = 0; j < 8; ++j)
            #pragma unroll
            for (int e = 0; e < 4; ++e) acc[i][j][e] = 0.f;

    // ---- cp.async loader: thread t -> row t (0..127), 8x16B chunks ----
    const int lr = tid;
    const u32 lsw = (u32)(lr & 7);
    const u32 rowb = (u32)lr * 128u;
    const __half* gA = A + (size_t)(m0 + lr) * lda;
    const __half* gB = B + (size_t)(n0 + lr) * ldb;

    auto load_stage = [&](int s, int k0) {          // k0 in half elements
        const u32 b = sb + (u32)s * ST_BYTES;
        #pragma unroll
        for (int j = 0; j < 8; ++j) {
            const u32 off = rowb + (((u32)j ^ lsw) << 4);
            cpa16(b +           off, gA + k0 + j * 8);
            cpa16(b + 16384u +  off, gB + k0 + j * 8);
        }
        CP_COMMIT();
    };

    const int nch = K >> 6;
    load_stage(0, 0);

    // ---- ldmatrix lane maps ----
    const int rr = lane & 7;
    const int rA = lane & 15, cA = lane >> 4;
    const u32 aBase = (u32)(wm * 64 + rA) * 128u;
    // B pair LDSM4: lane group g: row = wn*64 + pair*16 + (g>>1)*8 + rr, col-parity g&1
    const int g   = lane >> 3;
    const int gB1 = g & 1;
    const u32 bBase = (u32)(wn * 64 + ((g >> 1) << 3) + rr) * 128u;
    u32 cAo[4], cBo[4];
    #pragma unroll
    for (int ks = 0; ks < 4; ++ks) {
        cAo[ks] = (u32)(((ks * 2 + cA)  ^ rr) << 4);
        cBo[ks] = (u32)(((ks * 2 + gB1) ^ rr) << 4);
    }

    for (int c = 0; c < nch; ++c) {
        CP_WAIT(0);
        __syncthreads();
        if (c + 1 < nch)
            load_stage((c + 1) & 1, (c + 1) * 64);

        const u32 base  = sb + (u32)(c & 1) * ST_BYTES;
        const u32 baseB = base + 16384u;
        #pragma unroll
        for (int ks = 0; ks < 4; ++ks) {
            u32 bb[8][2];
            #pragma unroll
            for (int p = 0; p < 4; ++p)
                LDSM4(bb[2*p][0], bb[2*p][1], bb[2*p+1][0], bb[2*p+1][1],
                      baseB + bBase + (u32)p * 2048u + cBo[ks]);
            #pragma unroll
            for (int am = 0; am < 4; ++am) {
                u32 aa[4];
                LDSM4(aa[0], aa[1], aa[2], aa[3], base + aBase + (u32)am * 2048u + cAo[ks]);
                #pragma unroll
                for (int bn = 0; bn < 8; ++bn)
                    mma_f16(acc[am][bn], aa, bb[bn]);
            }
        }
    }

    // ======================= epilogue =======================
    const int q = lane >> 2, tq = lane & 3;

    if constexpr (MODE == 1) {
        __syncthreads();
        // transpose 128x128 tile through smem (u16 = half bits), stride 132
        u16* T = reinterpret_cast<u16*>(smem_ptr);
        #pragma unroll
        for (int am = 0; am < 4; ++am)
            #pragma unroll
            for (int bn = 0; bn < 8; ++bn)
                #pragma unroll
                for (int e = 0; e < 4; ++e) {
                    const int ml = wm * 64 + am * 16 + q + (e >> 1) * 8;
                    const int nl = wn * 64 + bn * 8 + 2 * tq + (e & 1);
                    T[nl * 132 + ml] = h_bits(__float2half_rn(acc[am][bn][e] + bias[n0 + nl]));
                }
        __syncthreads();
        const int d = tid;
        const int b = m0 >> 11;
        const size_t idx = ((size_t)b * CC + (n0 + d)) * TT + (m0 & 2047);
        #pragma unroll
        for (int i = 0; i < 128; i += 8) {
            u32 w[4];
            #pragma unroll
            for (int p = 0; p < 4; ++p) {
                const u32 t0 = (u32)T[d * 132 + i + 2 * p];
                const u32 t1 = (u32)T[d * 132 + i + 2 * p + 1];
                w[p] = t0 | (t1 << 16);
            }
            *reinterpret_cast<uint4*>(outH + idx + i) = make_uint4(w[0], w[1], w[2], w[3]);
        }
        return;
    } else {

    if (MODE == 0) outH += z * sCz;
    else           outF += z * sCz;

    #pragma unroll
    for (int am = 0; am < 4; ++am)
        #pragma unroll
        for (int e2 = 0; e2 < 2; ++e2) {
            const int gm = m0 + wm * 64 + am * 16 + q + e2 * 8;
            #pragma unroll
            for (int bn = 0; bn < 8; ++bn) {
                const int gn = n0 + wn * 64 + bn * 8 + 2 * tq;
                float v0 = acc[am][bn][e2 * 2 + 0];
                float v1 = acc[am][bn][e2 * 2 + 1];
                if (MODE == 0) {
                    if (bias) { v0 += bias[gn]; v1 += bias[gn + 1]; }
                    *reinterpret_cast<u32*>(outH + (size_t)gm * ldc + gn) =
                        pack_h2(__float2half_rn(v0), __float2half_rn(v1));
                } else if (MODE == 2) {
                    float2 val; val.x = v0 * scale; val.y = v1 * scale;
                    *reinterpret_cast<float2*>(outF + (size_t)gm * ldc + gn) = val;
                } else {
                    float2 val; val.x = v0 + bias[gn]; val.y = v1 + bias[gn + 1];
                    *reinterpret_cast<float2*>(outF + (size_t)gm * ldc + gn) = val;
                }
            }
        }
    }
}

// ======================= convert fp32 -> half =======================
__global__ void __launch_bounds__(256) cvt_kernel(
    const float* __restrict__ x, __half* __restrict__ o, int n4)
{
    int i = blockIdx.x * 256 + threadIdx.x;
    if (i >= n4) return;
    float4 v = reinterpret_cast<const float4*>(x)[i];
    uint2 w;
    w.x = pack_h2(__float2half_rn(v.x), __float2half_rn(v.y));
    w.y = pack_h2(__float2half_rn(v.z), __float2half_rn(v.w));
    *reinterpret_cast<uint2*>(o + 4*(size_t)i) = w;
}

__global__ void __launch_bounds__(256) cvt_w4_kernel(
    const float* __restrict__ w0, const float* __restrict__ w1,
    const float* __restrict__ w2, const float* __restrict__ w3,
    __half* __restrict__ o)
{
    const int mat = blockIdx.y;
    const float* src = (mat == 0) ? w0 : (mat == 1) ? w1 : (mat == 2) ? w2 : w3;
    const size_t off = (size_t)mat * CC * CC;
    int i = blockIdx.x * 256 + threadIdx.x;
    float4 v = reinterpret_cast<const float4*>(src)[i];
    uint2 w;
    w.x = pack_h2(__float2half_rn(v.x), __float2half_rn(v.y));
    w.y = pack_h2(__float2half_rn(v.z), __float2half_rn(v.w));
    *reinterpret_cast<uint2*>(o + off + 4*(size_t)i) = w;
}

// ======================= softmax (fp32 in, half out) =======================
__global__ void __launch_bounds__(256) softmax_kernel(
    const float* __restrict__ S, __half* __restrict__ P)
{
    __shared__ float red[8];
    __shared__ float sM, sInv;
    const size_t row = blockIdx.x;
    const float4* src = reinterpret_cast<const float4*>(S + row * TT);
    const int t = threadIdx.x, w = t >> 5, ln = t & 31;

    float4 a = src[t], b2 = src[t + 256];
    float mx = fmaxf(fmaxf(fmaxf(a.x, a.y), fmaxf(a.z, a.w)),
                     fmaxf(fmaxf(b2.x, b2.y), fmaxf(b2.z, b2.w)));
    #pragma unroll
    for (int o = 16; o; o >>= 1) mx = fmaxf(mx, __shfl_xor_sync(0xffffffffu, mx, o));
    if (ln == 0) red[w] = mx;
    __syncthreads();
    if (t == 0) {
        float m = red[0];
        #pragma unroll
        for (int i = 1; i < 8; ++i) m = fmaxf(m, red[i]);
        sM = m;
    }
    __syncthreads();
    const float M = sM;

    float e[8];
    e[0] = __expf(a.x - M);  e[1] = __expf(a.y - M);
    e[2] = __expf(a.z - M);  e[3] = __expf(a.w - M);
    e[4] = __expf(b2.x - M); e[5] = __expf(b2.y - M);
    e[6] = __expf(b2.z - M); e[7] = __expf(b2.w - M);
    float sm = e[0]+e[1]+e[2]+e[3]+e[4]+e[5]+e[6]+e[7];
    #pragma unroll
    for (int o = 16; o; o >>= 1) sm += __shfl_xor_sync(0xffffffffu, sm, o);
    __syncthreads();
    if (ln == 0) red[w] = sm;
    __syncthreads();
    if (t == 0) {
        float ssum = 0.f;
        #pragma unroll
        for (int i = 0; i < 8; ++i) ssum += red[i];
        sInv = 1.0f / ssum;
    }
    __syncthreads();
    const float inv = sInv;

    #pragma unroll
    for (int half = 0; half < 2; ++half) {
        uint2 w2o;
        w2o.x = pack_h2(__float2half_rn(e[half*4 + 0] * inv), __float2half_rn(e[half*4 + 1] * inv));
        w2o.y = pack_h2(__float2half_rn(e[half*4 + 2] * inv), __float2half_rn(e[half*4 + 3] * inv));
        size_t off = row * TT + (size_t)(t + half*256) * 4;
        *reinterpret_cast<uint2*>(P + off) = w2o;
    }
}

// ======================= host launch =======================
static void* sym_addr(const void* s) {
    void* p = nullptr;
    cudaGetSymbolAddress(&p, s);
    return p;
}

extern "C" void kernel_launch(void* const* d_in, const int* in_sizes, int n_in,
                              void* d_out, int out_size) {
    (void)in_sizes; (void)n_in; (void)out_size;
    const float* x  = (const float*)d_in[0];
    const float* Wq = (const float*)d_in[1];
    const float* bq = (const float*)d_in[2];
    const float* Wk = (const float*)d_in[3];
    const float* bk = (const float*)d_in[4];
    const float* Wv = (const float*)d_in[5];
    const float* bv = (const float*)d_in[6];
    const float* Wo = (const float*)d_in[7];
    const float* bo = (const float*)d_in[8];
    float* out = (float*)d_out;

    __half* xh = (__half*)sym_addr(g_xh);
    __half* wh = (__half*)sym_addr(g_wh);
    __half* qq = (__half*)sym_addr(g_q);
    __half* kk = (__half*)sym_addr(g_k);
    __half* vt = (__half*)sym_addr(g_vt);
    float*  sS = (float*)sym_addr(g_s);
    __half* pp = (__half*)sym_addr(g_p);
    __half* cc = (__half*)sym_addr(g_c);

    cudaFuncSetAttribute(gemm_f16<0>, cudaFuncAttributeMaxDynamicSharedMemorySize, SMEM_BYTES);
    cudaFuncSetAttribute(gemm_f16<1>, cudaFuncAttributeMaxDynamicSharedMemorySize, SMEM_BYTES);
    cudaFuncSetAttribute(gemm_f16<2>, cudaFuncAttributeMaxDynamicSharedMemorySize, SMEM_BYTES);
    cudaFuncSetAttribute(gemm_f16<3>, cudaFuncAttributeMaxDynamicSharedMemorySize, SMEM_BYTES);

    // convert inputs to half
    cvt_kernel<<<(MROWS*CC/4 + 255)/256, 256>>>(x, xh, MROWS*CC/4);
    dim3 gW(CC*CC/4/256, 4);
    cvt_w4_kernel<<<gW, 256>>>(Wq, Wk, Wv, Wo, wh);

    dim3 gProj(MROWS/128, CC/128, 1);     // (64, 8, 1)
    // Q = x Wq^T + bq (half out)
    gemm_f16<0><<<gProj, 128, SMEM_BYTES>>>(xh, wh + 0*(size_t)CC*CC,
        CC, CC, CC, 0, 0, 0, bq, 1.f, qq, nullptr, CC);
    // K
    gemm_f16<0><<<gProj, 128, SMEM_BYTES>>>(xh, wh + 1*(size_t)CC*CC,
        CC, CC, CC, 0, 0, 0, bk, 1.f, kk, nullptr, CC);
    // V -> transposed half store vt[b][d][s]
    gemm_f16<1><<<gProj, 128, SMEM_BYTES>>>(xh, wh + 2*(size_t)CC*CC,
        CC, CC, CC, 0, 0, 0, bv, 1.f, vt, nullptr, 0);

    // scores = Q K^T / 32 (per batch, fp32 out)
    dim3 gScore(TT/128, TT/128, BN);      // (16, 16, 4)
    gemm_f16<2><<<gScore, 128, SMEM_BYTES>>>(qq, kk,
        CC, CC, CC, (long long)TT*CC, (long long)TT*CC, (long long)TT*TT,
        nullptr, 0.03125f, nullptr, sS, TT);

    // softmax (writes half P)
    softmax_kernel<<<MROWS, 256>>>(sS, pp);

    // ctx = P V (A = P [t][s], B = vt [d][s], per batch; half out)
    dim3 gPV(TT/128, CC/128, BN);         // (16, 8, 4)
    gemm_f16<0><<<gPV, 128, SMEM_BYTES>>>(pp, vt,
        TT, TT, TT, (long long)TT*TT, (long long)CC*TT, (long long)TT*CC,
        nullptr, 1.f, cc, nullptr, CC);

    // out = ctx Wo^T + bo (fp32 -> d_out)
    gemm_f16<3><<<gProj, 128, SMEM_BYTES>>>(cc, wh + 3*(size_t)CC*CC,
        CC, CC, CC, 0, 0, 0, bo, 1.f, nullptr, out, CC);
}